// round 9
// baseline (speedup 1.0000x reference)
#include <cuda_runtime.h>
#include <math.h>

#define NN 100000
#define EE 200000
#define H 128
#define NH (NN*H)
#define NGROUP 24   // 8 levels x 3 gate types (level 0 unused)

typedef unsigned long long u64;

// packed f32x2 helpers (Blackwell FFMA2 path)
#define FMA2(d, a, b) asm("fma.rn.f32x2 %0, %1, %2, %0;" : "+l"(d) : "l"(a), "l"(b))
#define SQUAD_BAR(s) asm volatile("bar.sync %0, %1;" :: "r"((s)+1), "r"(128) : "memory")
__device__ __forceinline__ u64 pk2(float lo, float hi) {
    u64 r; asm("mov.b64 %0, {%1, %2};" : "=l"(r) : "f"(lo), "f"(hi)); return r;
}
__device__ __forceinline__ void upk2(u64 v, float& lo, float& hi) {
    asm("mov.b64 {%0, %1}, %2;" : "=f"(lo), "=f"(hi) : "l"(v));
}

// ---------------- scratch (static device memory; no allocs) ----------------
__device__ float g_msg[NN*H];
__device__ float g_hstype[6*H];
__device__ float g_t1[3*6*H];            // t1[gi][g] = hstype[g]@W1a + b1
__device__ float g_w3T[3][H*H];
__device__ float g_W4[3][H*384];         // W4 = W3 @ wih^T, k-major [k][m]
__device__ float g_c3[3*384];            // c3 = b3 @ wih^T
__device__ int   g_deg[NN];
__device__ int   g_ecnt[NGROUP];
__device__ int   g_ncnt[NGROUP];
__device__ int   g_ebuck[NGROUP][EE];
__device__ int   g_nbuck[NGROUP][NN];

// ---------------- setup kernels ----------------
__global__ void zcnt_k() {
    int t = threadIdx.x;
    if (t < NGROUP) { g_ecnt[t] = 0; g_ncnt[t] = 0; }
}

__global__ void hs_type_k(const float* __restrict__ Ws, const float* __restrict__ Wt,
                          const float* __restrict__ hsW, const float* __restrict__ hsb) {
    int g = blockIdx.x, j = threadIdx.x;
    __shared__ float st[256];
    st[j]       = Ws[g*H + j];
    st[128 + j] = Wt[g*H + j];
    __syncthreads();
    float acc = hsb[j];
    #pragma unroll 8
    for (int k = 0; k < 256; k++) acc = fmaf(st[k], hsW[k*H + j], acc);
    g_hstype[g*H + j] = acc;
}

__global__ void t1_k(const float* __restrict__ w1, const float* __restrict__ b1) {
    int g = blockIdx.x, gi = blockIdx.y, j = threadIdx.x;
    __shared__ float sh[H];
    sh[j] = g_hstype[g*H + j];
    __syncthreads();
    float acc = b1[gi*H + j];
    const float* W = w1 + (size_t)gi*2*H*H;
    #pragma unroll 8
    for (int k = 0; k < H; k++) acc = fmaf(sh[k], W[k*H + j], acc);
    g_t1[(gi*6 + g)*H + j] = acc;
}

__global__ void w3T_k(const float* __restrict__ w3) {
    int idx = blockIdx.x*blockDim.x + threadIdx.x;
    if (idx >= 3*H*H) return;
    int gi = idx / (H*H);
    int r  = idx % (H*H);
    int k = r / H, j = r % H;
    g_w3T[gi][j*H + k] = w3[(size_t)gi*H*H + k*H + j];
}

__global__ void w4_k(const float* __restrict__ wih) {
    int gi = blockIdx.y;
    int m0 = blockIdx.x * 8;
    int k  = threadIdx.x;
    __shared__ float sw[8][H];
    #pragma unroll
    for (int mm = 0; mm < 8; mm++) sw[mm][k] = wih[((size_t)gi*384 + m0 + mm)*H + k];
    __syncthreads();
    float acc[8];
    #pragma unroll
    for (int mm = 0; mm < 8; mm++) acc[mm] = 0.f;
    for (int j = 0; j < H; j++) {
        float v = g_w3T[gi][j*H + k];
        #pragma unroll
        for (int mm = 0; mm < 8; mm++) acc[mm] = fmaf(v, sw[mm][j], acc[mm]);
    }
    #pragma unroll
    for (int mm = 0; mm < 8; mm++) g_W4[gi][k*384 + m0 + mm] = acc[mm];
}

__global__ void c3_k(const float* __restrict__ b3, const float* __restrict__ wih) {
    int gi = blockIdx.x, m = threadIdx.x;
    __shared__ float sb[H];
    if (m < H) sb[m] = b3[gi*H + m];
    __syncthreads();
    float acc = 0.f;
    for (int j = 0; j < H; j++) acc = fmaf(sb[j], wih[((size_t)gi*384 + m)*H + j], acc);
    g_c3[gi*384 + m] = acc;
}

__global__ void scatter_k(const int* __restrict__ gate, float* __restrict__ out) {
    int j = threadIdx.x;
    int r = j >> 5, c = j & 31;
    float4* out4 = (float4*)out;
    const float4* ht4 = (const float4*)g_hstype;
    float4 z4 = make_float4(0.f, 0.f, 0.f, 0.f);
    for (int i0 = blockIdx.x*4; i0 < NN; i0 += gridDim.x*4) {
        int i = i0 + r;
        if (i < NN) {
            int g = gate[i];
            out4[(size_t)i*32 + c]        = ht4[g*32 + c];
            out4[(size_t)(NN + i)*32 + c] = z4;
        }
    }
    for (int i = blockIdx.x*blockDim.x + j; i < NN; i += gridDim.x*blockDim.x)
        g_deg[i] = 0;
}

__device__ __forceinline__ int gate_to_gi(int g) {
    // GATE_CODES = (3, 2, 5)
    return (g == 3) ? 0 : (g == 2) ? 1 : (g == 5) ? 2 : -1;
}

__global__ void bedge_k(const int* __restrict__ ei, const int* __restrict__ gate,
                        const int* __restrict__ lvl) {
    for (int e = blockIdx.x*blockDim.x + threadIdx.x; e < EE; e += gridDim.x*blockDim.x) {
        int d = ei[EE + e];
        int gi = gate_to_gi(gate[d]);
        int l = lvl[d];
        if (gi >= 0 && l >= 1) {
            int grp = l*3 + gi;
            int p = atomicAdd(&g_ecnt[grp], 1);
            g_ebuck[grp][p] = e;
            atomicAdd(&g_deg[d], 1);
        }
    }
}

__global__ void bnode_k(const int* __restrict__ gate, const int* __restrict__ lvl) {
    for (int i = blockIdx.x*blockDim.x + threadIdx.x; i < NN; i += gridDim.x*blockDim.x) {
        int gi = gate_to_gi(gate[i]);
        int l = lvl[i];
        if (gi >= 0 && l >= 1) {
            int grp = l*3 + gi;
            int p = atomicAdd(&g_ncnt[grp], 1);
            g_nbuck[grp][p] = i;
        }
    }
}

__global__ void zmsg_k() {
    int j = threadIdx.x;
    for (int grp = 0; grp < NGROUP; grp++) {
        int cnt = g_ncnt[grp];
        for (int t = blockIdx.x; t < cnt; t += gridDim.x) {
            int node = g_nbuck[grp][t];
            g_msg[(size_t)node*H + j] = 0.f;
        }
    }
}

// ---------------- edge MLP: smem-resident weights, 2 squads per block ----------------
#define ETILE 16
// dyn smem: sW1p[64*128]u64 | sW2p[64*128]u64 | sx[2][ETILE*H] | sh1[2][ETILE*H] | idx[2][3*ETILE]
__global__ void __launch_bounds__(256, 1) emlp_k(
    int level, const int* __restrict__ ei, const int* __restrict__ gate,
    const float* __restrict__ w1,
    const float* __restrict__ w2, const float* __restrict__ b2,
    const float* __restrict__ nodes)
{
    extern __shared__ __align__(16) char dsm[];
    u64*   sW1 = (u64*)dsm;                    // packed (k,k+1) pairs, [kp][j]
    u64*   sW2 = sW1 + 64*H;
    float* sxa = (float*)(sW2 + 64*H);
    float* sha = sxa + 2*ETILE*H;
    int*   sia = (int*)(sha + 2*ETILE*H);

    const int tid = threadIdx.x;
    const int squad = tid >> 7;
    const int j = tid & 127;
    const int gi = blockIdx.y;
    const int grp  = level*3 + gi;
    const int cnt  = g_ecnt[grp];
    const int ntile = (cnt + ETILE - 1) / ETILE;
    const float* hf  = nodes + NH;
    const float* W1b = w1 + (size_t)gi*2*H*H + (size_t)H*H;
    const float* W2  = w2 + (size_t)gi*H*H;
    const float  B2  = b2[gi*H + j];
    const float* T1  = g_t1 + gi*6*H;

    // cooperative weight load + f32x2 pack (once per block)
    for (int kp = squad; kp < 64; kp += 2) {
        sW1[kp*H + j] = pk2(W1b[(2*kp)*H + j], W1b[(2*kp+1)*H + j]);
        sW2[kp*H + j] = pk2(W2 [(2*kp)*H + j], W2 [(2*kp+1)*H + j]);
    }
    __syncthreads();

    float* sx  = sxa + squad*ETILE*H;
    float* sh1 = sha + squad*ETILE*H;
    int*  ssrc = sia + squad*3*ETILE;
    int*  sdst = ssrc + ETILE;
    int*  sgat = sdst + ETILE;

    for (int tile = blockIdx.x*2 + squad; tile < ntile; tile += gridDim.x*2) {
        const int base = tile * ETILE;
        const int ne = min(ETILE, cnt - base);
        if (j < ETILE) {
            int e = g_ebuck[grp][base + (j < ne ? j : 0)];
            int s = ei[e];
            ssrc[j] = s;
            sdst[j] = ei[EE + e];
            sgat[j] = gate[s];
        }
        SQUAD_BAR(squad);
        #pragma unroll
        for (int t = 0; t < ETILE; t++)
            sx[t*H + j] = hf[(size_t)ssrc[t]*H + j];
        SQUAD_BAR(squad);

        u64 acc[ETILE];
        // layer 1 (hf part; hs part + b1 folded into t1 table)
        #pragma unroll
        for (int t = 0; t < ETILE; t++) acc[t] = pk2(T1[sgat[t]*H + j], 0.f);
        for (int k = 0; k < H; k += 4) {
            u64 w01 = sW1[(k>>1)*H + j];
            u64 w23 = sW1[(k>>1)*H + H + j];
            #pragma unroll
            for (int t = 0; t < ETILE; t++) {
                ulonglong2 xv = *reinterpret_cast<const ulonglong2*>(&sx[t*H + k]);
                FMA2(acc[t], xv.x, w01);
                FMA2(acc[t], xv.y, w23);
            }
        }
        #pragma unroll
        for (int t = 0; t < ETILE; t++) {
            float lo, hi; upk2(acc[t], lo, hi);
            sh1[t*H + j] = fmaxf(lo + hi, 0.f);
        }
        SQUAD_BAR(squad);

        // layer 2
        #pragma unroll
        for (int t = 0; t < ETILE; t++) acc[t] = pk2(B2, 0.f);
        for (int k = 0; k < H; k += 4) {
            u64 w01 = sW2[(k>>1)*H + j];
            u64 w23 = sW2[(k>>1)*H + H + j];
            #pragma unroll
            for (int t = 0; t < ETILE; t++) {
                ulonglong2 xv = *reinterpret_cast<const ulonglong2*>(&sh1[t*H + k]);
                FMA2(acc[t], xv.x, w01);
                FMA2(acc[t], xv.y, w23);
            }
        }
        for (int t = 0; t < ne; t++) {
            float lo, hi; upk2(acc[t], lo, hi);
            atomicAdd(&g_msg[(size_t)sdst[t]*H + j], fmaxf(lo + hi, 0.f));
        }
        SQUAD_BAR(squad);
    }
}

// ---------------- GRU: smem-resident W4, 2 squads, FFMA2 over t-pairs ----------------
#define NTILE 16
#define MST 18
// dyn smem: sWT[H*384] | smt[2][H*MST] | snode/sdeg[2][2*NTILE]
__global__ void __launch_bounds__(256, 1) gru_k(
    int level,
    const float* __restrict__ bih, const float* __restrict__ bhh,
    float* __restrict__ hfout)
{
    extern __shared__ __align__(16) char dsm[];
    float* sWT = (float*)dsm;                  // [k][384]
    float* smta = sWT + H*384;
    int*   snia = (int*)(smta + 2*H*MST);

    const int tid = threadIdx.x;
    const int squad = tid >> 7;
    const int j = tid & 127;
    const int gi = blockIdx.y;
    const int grp  = level*3 + gi;
    const int cnt  = g_ncnt[grp];
    const int ntile = (cnt + NTILE - 1) / NTILE;
    const float* WT = g_W4[gi];
    const float br = bih[gi*384 + j]       + bhh[gi*384 + j];
    const float bz = bih[gi*384 + 128 + j] + bhh[gi*384 + 128 + j];
    const float bn = bih[gi*384 + 256 + j];
    const float hn = bhh[gi*384 + 256 + j];
    const float c3r = g_c3[gi*384 + j];
    const float c3z = g_c3[gi*384 + 128 + j];
    const float c3n = g_c3[gi*384 + 256 + j];

    for (int i = tid; i < H*384; i += 256) sWT[i] = WT[i];
    __syncthreads();

    float* smt  = smta + squad*H*MST;
    int* snode  = snia + squad*2*NTILE;
    int* sdeg   = snode + NTILE;

    for (int tile = blockIdx.x*2 + squad; tile < ntile; tile += gridDim.x*2) {
        const int base = tile * NTILE;
        const int nn = min(NTILE, cnt - base);
        if (j < NTILE) {
            int node = g_nbuck[grp][base + (j < nn ? j : 0)];
            snode[j] = node;
            sdeg[j]  = g_deg[node];
        }
        SQUAD_BAR(squad);
        #pragma unroll
        for (int t = 0; t < NTILE; t++)
            smt[j*MST + t] = g_msg[(size_t)snode[t]*H + j];
        SQUAD_BAR(squad);

        u64 ar[NTILE/2], az[NTILE/2], an[NTILE/2];
        #pragma unroll
        for (int p = 0; p < NTILE/2; p++) { ar[p] = 0ull; az[p] = 0ull; an[p] = 0ull; }
        #pragma unroll 2
        for (int k = 0; k < H; k++) {
            float wr = sWT[k*384 + j];
            float wz = sWT[k*384 + 128 + j];
            float wn = sWT[k*384 + 256 + j];
            u64 wr2 = pk2(wr, wr), wz2 = pk2(wz, wz), wn2 = pk2(wn, wn);
            #pragma unroll
            for (int p = 0; p < NTILE/2; p++) {
                u64 x = *reinterpret_cast<const u64*>(&smt[k*MST + 2*p]);
                FMA2(ar[p], x, wr2);
                FMA2(az[p], x, wz2);
                FMA2(an[p], x, wn2);
            }
        }
        #pragma unroll
        for (int p = 0; p < NTILE/2; p++) {
            float arA, arB, azA, azB, anA, anB;
            upk2(ar[p], arA, arB);
            upk2(az[p], azA, azB);
            upk2(an[p], anA, anB);
            int t0 = 2*p, t1 = 2*p + 1;
            if (t0 < nn) {
                float dg = (float)sdeg[t0];
                float r = 1.f / (1.f + expf(-(arA + br + dg*c3r)));
                float z = 1.f / (1.f + expf(-(azA + bz + dg*c3z)));
                float nst = tanhf(anA + bn + dg*c3n + r * hn);
                hfout[(size_t)snode[t0]*H + j] = (1.f - z) * nst;
            }
            if (t1 < nn) {
                float dg = (float)sdeg[t1];
                float r = 1.f / (1.f + expf(-(arB + br + dg*c3r)));
                float z = 1.f / (1.f + expf(-(azB + bz + dg*c3z)));
                float nst = tanhf(anB + bn + dg*c3n + r * hn);
                hfout[(size_t)snode[t1]*H + j] = (1.f - z) * nst;
            }
        }
        SQUAD_BAR(squad);
    }
}

// ---------------- launch ----------------
extern "C" void kernel_launch(void* const* d_in, const int* in_sizes, int n_in,
                              void* d_out, int out_size) {
    const int*   gate = (const int*)d_in[0];
    const int*   lvl  = (const int*)d_in[1];
    const int*   ei   = (const int*)d_in[2];
    const float* Ws   = (const float*)d_in[3];
    const float* Wt   = (const float*)d_in[4];
    const float* hsW  = (const float*)d_in[5];
    const float* hsb  = (const float*)d_in[6];
    const float* w1   = (const float*)d_in[7];
    const float* b1   = (const float*)d_in[8];
    const float* w2   = (const float*)d_in[9];
    const float* b2   = (const float*)d_in[10];
    const float* w3   = (const float*)d_in[11];
    const float* b3   = (const float*)d_in[12];
    const float* wih  = (const float*)d_in[13];
    // d_in[14] = gru_whh: provably unused (h_old == 0 for every updated node)
    const float* bih  = (const float*)d_in[15];
    const float* bhh  = (const float*)d_in[16];
    float* out = (float*)d_out;   // [0, NH) = hs, [NH, 2NH) = hf

    const int smem_e = 64*H*8*2 + 2*ETILE*H*4*2 + 2*3*ETILE*4;          // ~160.4 KB
    const int smem_g = H*384*4 + 2*H*MST*4 + 2*2*NTILE*4;               // ~210.4 KB
    cudaFuncSetAttribute(emlp_k, cudaFuncAttributeMaxDynamicSharedMemorySize, smem_e);
    cudaFuncSetAttribute(gru_k,  cudaFuncAttributeMaxDynamicSharedMemorySize, smem_g);

    zcnt_k<<<1, 32>>>();
    hs_type_k<<<6, 128>>>(Ws, Wt, hsW, hsb);
    t1_k<<<dim3(6, 3), 128>>>(w1, b1);
    w3T_k<<<(3*H*H + 255)/256, 256>>>(w3);
    w4_k<<<dim3(48, 3), 128>>>(wih);
    c3_k<<<3, 384>>>(b3, wih);
    scatter_k<<<2048, 128>>>(gate, out);
    bedge_k<<<512, 256>>>(ei, gate, lvl);
    bnode_k<<<256, 256>>>(gate, lvl);
    zmsg_k<<<2048, 128>>>();

    for (int level = 1; level < 8; level++) {
        emlp_k<<<dim3(49, 3), 256, smem_e>>>(level, ei, gate, w1, w2, b2, out);
        gru_k<<<dim3(48, 3), 256, smem_g>>>(level, bih, bhh, out + NH);
    }
}

// round 10
// speedup vs baseline: 1.3478x; 1.3478x over previous
#include <cuda_runtime.h>
#include <math.h>

#define NN 100000
#define EE 200000
#define H 128
#define NH (NN*H)
#define NGROUP 24   // 8 levels x 3 gate types (level 0 unused)

typedef unsigned long long u64;

// packed f32x2 helpers (Blackwell FFMA2 path)
#define FMA2(d, a, b) asm("fma.rn.f32x2 %0, %1, %2, %0;" : "+l"(d) : "l"(a), "l"(b))
__device__ __forceinline__ u64 pk2(float lo, float hi) {
    u64 r; asm("mov.b64 %0, {%1, %2};" : "=l"(r) : "f"(lo), "f"(hi)); return r;
}
__device__ __forceinline__ void upk2(u64 v, float& lo, float& hi) {
    asm("mov.b64 {%0, %1}, %2;" : "=f"(lo), "=f"(hi) : "l"(v));
}

// ---------------- scratch (static device memory; no allocs) ----------------
__device__ float g_msg[NN*H];
__device__ float g_hstype[6*H];
__device__ float g_t1[3*6*H];            // t1[gi][g] = hstype[g]@W1a + b1
__device__ float g_w3T[3][H*H];
__device__ float g_W4[3][H*384];         // W4 = W3 @ wih^T, k-major [k][m]
__device__ float g_c3[3*384];            // c3 = b3 @ wih^T
__device__ int   g_deg[NN];
__device__ int   g_ecnt[NGROUP];
__device__ int   g_ncnt[NGROUP];
__device__ int   g_ebuck[NGROUP][EE];
__device__ int   g_nbuck[NGROUP][NN];

__device__ __forceinline__ int gate_to_gi(int g) {
    // GATE_CODES = (3, 2, 5)
    return (g == 3) ? 0 : (g == 2) ? 1 : (g == 5) ? 2 : -1;
}

// ---------------- setupA: all input-independent-order work ----------------
// b=0: zcnt | b in [1,7): hs_type | b in [7,10): c3 | b in [10,394): w3T | b in [394,1176): zero deg
__global__ void __launch_bounds__(128) setupA_k(
    const float* __restrict__ Ws, const float* __restrict__ Wt,
    const float* __restrict__ hsW, const float* __restrict__ hsb,
    const float* __restrict__ b3, const float* __restrict__ wih,
    const float* __restrict__ w3)
{
    __shared__ float sbuf[256];
    const int b = blockIdx.x, j = threadIdx.x;
    if (b == 0) {
        if (j < NGROUP) { g_ecnt[j] = 0; g_ncnt[j] = 0; }
    } else if (b < 7) {               // hs_type, g = b-1
        int g = b - 1;
        sbuf[j]       = Ws[g*H + j];
        sbuf[128 + j] = Wt[g*H + j];
        __syncthreads();
        float acc = hsb[j];
        #pragma unroll 8
        for (int k = 0; k < 256; k++) acc = fmaf(sbuf[k], hsW[k*H + j], acc);
        g_hstype[g*H + j] = acc;
    } else if (b < 10) {              // c3, gi = b-7
        int gi = b - 7;
        sbuf[j] = b3[gi*H + j];
        __syncthreads();
        for (int m = j; m < 384; m += 128) {
            float acc = 0.f;
            for (int k = 0; k < H; k++) acc = fmaf(sbuf[k], wih[((size_t)gi*384 + m)*H + k], acc);
            g_c3[gi*384 + m] = acc;
        }
    } else if (b < 394) {             // w3T
        int idx = (b - 10)*128 + j;   // < 3*128*128 = 49152
        int gi = idx / (H*H);
        int r  = idx % (H*H);
        int k = r / H, jj = r % H;
        g_w3T[gi][jj*H + k] = w3[(size_t)gi*H*H + k*H + jj];
    } else {                          // zero g_deg
        int i = (b - 394)*128 + j;
        if (i < NN) g_deg[i] = 0;
    }
}

// ---------------- setupB: depends only on setupA ----------------
// [0,18) t1 | [18,162) w4 | [162,674) scatter | [674,1186) bedge | [1186,1442) bnode
__global__ void __launch_bounds__(128) setupB_k(
    const int* __restrict__ gate, const int* __restrict__ lvl, const int* __restrict__ ei,
    const float* __restrict__ w1, const float* __restrict__ b1,
    const float* __restrict__ wih, float* __restrict__ out)
{
    __shared__ float sbuf[1024];
    const int b = blockIdx.x, j = threadIdx.x;
    if (b < 18) {                     // t1: g = b/3, gi = b%3
        int g = b / 3, gi = b % 3;
        sbuf[j] = g_hstype[g*H + j];
        __syncthreads();
        float acc = b1[gi*H + j];
        const float* W = w1 + (size_t)gi*2*H*H;
        #pragma unroll 8
        for (int k = 0; k < H; k++) acc = fmaf(sbuf[k], W[k*H + j], acc);
        g_t1[(gi*6 + g)*H + j] = acc;
    } else if (b < 162) {             // w4: 144 blocks
        int idx = b - 18;
        int gi = idx / 48;
        int m0 = (idx % 48) * 8;
        float (*sw)[H] = (float(*)[H])sbuf;
        #pragma unroll
        for (int mm = 0; mm < 8; mm++) sw[mm][j] = wih[((size_t)gi*384 + m0 + mm)*H + j];
        __syncthreads();
        float acc[8];
        #pragma unroll
        for (int mm = 0; mm < 8; mm++) acc[mm] = 0.f;
        for (int kk = 0; kk < H; kk++) {
            float v = g_w3T[gi][kk*H + j];
            #pragma unroll
            for (int mm = 0; mm < 8; mm++) acc[mm] = fmaf(v, sw[mm][kk], acc[mm]);
        }
        #pragma unroll
        for (int mm = 0; mm < 8; mm++) g_W4[gi][j*384 + m0 + mm] = acc[mm];
    } else if (b < 674) {             // scatter hs/hf
        int r = j >> 5, c = j & 31;
        float4* out4 = (float4*)out;
        const float4* ht4 = (const float4*)g_hstype;
        float4 z4 = make_float4(0.f, 0.f, 0.f, 0.f);
        for (int i0 = (b - 162)*4; i0 < NN; i0 += 512*4) {
            int i = i0 + r;
            if (i < NN) {
                int g = gate[i];
                out4[(size_t)i*32 + c]        = ht4[g*32 + c];
                out4[(size_t)(NN + i)*32 + c] = z4;
            }
        }
    } else if (b < 1186) {            // bedge
        for (int e = (b - 674)*128 + j; e < EE; e += 512*128) {
            int d = ei[EE + e];
            int gi = gate_to_gi(gate[d]);
            int l = lvl[d];
            if (gi >= 0 && l >= 1) {
                int grp = l*3 + gi;
                int p = atomicAdd(&g_ecnt[grp], 1);
                g_ebuck[grp][p] = e;
                atomicAdd(&g_deg[d], 1);
            }
        }
    } else {                          // bnode
        for (int i = (b - 1186)*128 + j; i < NN; i += 256*128) {
            int gi = gate_to_gi(gate[i]);
            int l = lvl[i];
            if (gi >= 0 && l >= 1) {
                int grp = l*3 + gi;
                int p = atomicAdd(&g_ncnt[grp], 1);
                g_nbuck[grp][p] = i;
            }
        }
    }
}

// ---------------- setupC: zero msg rows of bucket nodes ----------------
__global__ void zmsg_k() {
    int j = threadIdx.x;
    for (int grp = 0; grp < NGROUP; grp++) {
        int cnt = g_ncnt[grp];
        for (int t = blockIdx.x; t < cnt; t += gridDim.x) {
            int node = g_nbuck[grp][t];
            g_msg[(size_t)node*H + j] = 0.f;
        }
    }
}

// ---------------- edge MLP: 64 threads, 2 output cols/thread, FFMA2 ----------------
#define ETILE 16
__global__ void __launch_bounds__(64) emlp_k(
    int level, const int* __restrict__ ei, const int* __restrict__ gate,
    const float* __restrict__ w1,
    const float* __restrict__ w2, const float* __restrict__ b2,
    const float* __restrict__ nodes)
{
    __shared__ __align__(16) float sx[ETILE*H];
    __shared__ __align__(16) float sh1[ETILE*H];
    __shared__ float sT1[6*H];
    __shared__ int ssrc[ETILE];
    __shared__ int sdst[ETILE];
    __shared__ int sgat[ETILE];
    const int j  = threadIdx.x;       // 0..63; cols j and j+64
    const int gi = blockIdx.y;
    const int grp  = level*3 + gi;
    const int cnt  = g_ecnt[grp];
    const int ntile = (cnt + ETILE - 1) / ETILE;
    const float* hf  = nodes + NH;
    const float* W1b = w1 + (size_t)gi*2*H*H + (size_t)H*H;   // hf rows 128..255
    const float* W2  = w2 + (size_t)gi*H*H;
    const float  B2a = b2[gi*H + j];
    const float  B2b = b2[gi*H + 64 + j];
    const float* T1  = g_t1 + gi*6*H;

    for (int i = j; i < 6*H; i += 64) sT1[i] = T1[i];
    __syncthreads();

    for (int tile = blockIdx.x; tile < ntile; tile += gridDim.x) {
        const int base = tile * ETILE;
        const int ne = min(ETILE, cnt - base);
        if (j < ETILE) {
            int e = g_ebuck[grp][base + (j < ne ? j : 0)];
            int s = ei[e];
            ssrc[j] = s;
            sdst[j] = ei[EE + e];
            sgat[j] = gate[s];
        }
        __syncthreads();
        #pragma unroll
        for (int t = 0; t < ETILE; t++) {
            sx[t*H + j]      = hf[(size_t)ssrc[t]*H + j];
            sx[t*H + 64 + j] = hf[(size_t)ssrc[t]*H + 64 + j];
        }
        __syncthreads();

        u64 a0[ETILE], a1[ETILE];
        // layer 1 (hf part; hs part + b1 folded into t1 table)
        #pragma unroll
        for (int t = 0; t < ETILE; t++) {
            a0[t] = pk2(sT1[sgat[t]*H + j], 0.f);
            a1[t] = pk2(sT1[sgat[t]*H + 64 + j], 0.f);
        }
        for (int k = 0; k < H; k += 4) {
            u64 wA01 = pk2(W1b[(k+0)*H + j],      W1b[(k+1)*H + j]);
            u64 wA23 = pk2(W1b[(k+2)*H + j],      W1b[(k+3)*H + j]);
            u64 wB01 = pk2(W1b[(k+0)*H + 64 + j], W1b[(k+1)*H + 64 + j]);
            u64 wB23 = pk2(W1b[(k+2)*H + 64 + j], W1b[(k+3)*H + 64 + j]);
            #pragma unroll
            for (int t = 0; t < ETILE; t++) {
                ulonglong2 xv = *reinterpret_cast<const ulonglong2*>(&sx[t*H + k]);
                FMA2(a0[t], xv.x, wA01);
                FMA2(a0[t], xv.y, wA23);
                FMA2(a1[t], xv.x, wB01);
                FMA2(a1[t], xv.y, wB23);
            }
        }
        #pragma unroll
        for (int t = 0; t < ETILE; t++) {
            float lo, hi;
            upk2(a0[t], lo, hi); sh1[t*H + j]      = fmaxf(lo + hi, 0.f);
            upk2(a1[t], lo, hi); sh1[t*H + 64 + j] = fmaxf(lo + hi, 0.f);
        }
        __syncthreads();

        // layer 2
        #pragma unroll
        for (int t = 0; t < ETILE; t++) { a0[t] = pk2(B2a, 0.f); a1[t] = pk2(B2b, 0.f); }
        for (int k = 0; k < H; k += 4) {
            u64 wA01 = pk2(W2[(k+0)*H + j],      W2[(k+1)*H + j]);
            u64 wA23 = pk2(W2[(k+2)*H + j],      W2[(k+3)*H + j]);
            u64 wB01 = pk2(W2[(k+0)*H + 64 + j], W2[(k+1)*H + 64 + j]);
            u64 wB23 = pk2(W2[(k+2)*H + 64 + j], W2[(k+3)*H + 64 + j]);
            #pragma unroll
            for (int t = 0; t < ETILE; t++) {
                ulonglong2 xv = *reinterpret_cast<const ulonglong2*>(&sh1[t*H + k]);
                FMA2(a0[t], xv.x, wA01);
                FMA2(a0[t], xv.y, wA23);
                FMA2(a1[t], xv.x, wB01);
                FMA2(a1[t], xv.y, wB23);
            }
        }
        for (int t = 0; t < ne; t++) {
            float lo, hi;
            upk2(a0[t], lo, hi);
            atomicAdd(&g_msg[(size_t)sdst[t]*H + j], fmaxf(lo + hi, 0.f));
            upk2(a1[t], lo, hi);
            atomicAdd(&g_msg[(size_t)sdst[t]*H + 64 + j], fmaxf(lo + hi, 0.f));
        }
        __syncthreads();
    }
}

// ---------------- per-level GRU (R7-measured version, unchanged) ----------------
#define NTILE 16
#define MST 18
__global__ void __launch_bounds__(128) gru_k(
    int level,
    const float* __restrict__ bih, const float* __restrict__ bhh,
    float* __restrict__ hfout)
{
    __shared__ __align__(16) float smt[H*MST];
    __shared__ int snode[NTILE];
    __shared__ int sdeg[NTILE];
    const int j  = threadIdx.x;
    const int gi = blockIdx.y;
    const int grp  = level*3 + gi;
    const int cnt  = g_ncnt[grp];
    const int ntile = (cnt + NTILE - 1) / NTILE;
    const float* WT = g_W4[gi];
    const float br = bih[gi*384 + j]       + bhh[gi*384 + j];
    const float bz = bih[gi*384 + 128 + j] + bhh[gi*384 + 128 + j];
    const float bn = bih[gi*384 + 256 + j];
    const float hn = bhh[gi*384 + 256 + j];
    const float c3r = g_c3[gi*384 + j];
    const float c3z = g_c3[gi*384 + 128 + j];
    const float c3n = g_c3[gi*384 + 256 + j];

    for (int tile = blockIdx.x; tile < ntile; tile += gridDim.x) {
        const int base = tile * NTILE;
        const int nn = min(NTILE, cnt - base);
        if (j < NTILE) {
            int node = g_nbuck[grp][base + (j < nn ? j : 0)];
            snode[j] = node;
            sdeg[j]  = g_deg[node];
        }
        __syncthreads();
        #pragma unroll
        for (int t = 0; t < NTILE; t++)
            smt[j*MST + t] = g_msg[(size_t)snode[t]*H + j];
        __syncthreads();

        u64 ar[NTILE/2], az[NTILE/2], an[NTILE/2];
        #pragma unroll
        for (int p = 0; p < NTILE/2; p++) { ar[p] = 0ull; az[p] = 0ull; an[p] = 0ull; }
        #pragma unroll 2
        for (int k = 0; k < H; k++) {
            float wr = WT[k*384 + j];
            float wz = WT[k*384 + 128 + j];
            float wn = WT[k*384 + 256 + j];
            u64 wr2 = pk2(wr, wr), wz2 = pk2(wz, wz), wn2 = pk2(wn, wn);
            #pragma unroll
            for (int p = 0; p < NTILE/2; p++) {
                u64 x = *reinterpret_cast<const u64*>(&smt[k*MST + 2*p]);
                FMA2(ar[p], x, wr2);
                FMA2(az[p], x, wz2);
                FMA2(an[p], x, wn2);
            }
        }
        #pragma unroll
        for (int p = 0; p < NTILE/2; p++) {
            float arA, arB, azA, azB, anA, anB;
            upk2(ar[p], arA, arB);
            upk2(az[p], azA, azB);
            upk2(an[p], anA, anB);
            int t0 = 2*p, t1 = 2*p + 1;
            if (t0 < nn) {
                float dg = (float)sdeg[t0];
                float r = 1.f / (1.f + expf(-(arA + br + dg*c3r)));
                float z = 1.f / (1.f + expf(-(azA + bz + dg*c3z)));
                float nst = tanhf(anA + bn + dg*c3n + r * hn);
                hfout[(size_t)snode[t0]*H + j] = (1.f - z) * nst;
            }
            if (t1 < nn) {
                float dg = (float)sdeg[t1];
                float r = 1.f / (1.f + expf(-(arB + br + dg*c3r)));
                float z = 1.f / (1.f + expf(-(azB + bz + dg*c3z)));
                float nst = tanhf(anB + bn + dg*c3n + r * hn);
                hfout[(size_t)snode[t1]*H + j] = (1.f - z) * nst;
            }
        }
        __syncthreads();
    }
}

// ---------------- launch ----------------
extern "C" void kernel_launch(void* const* d_in, const int* in_sizes, int n_in,
                              void* d_out, int out_size) {
    const int*   gate = (const int*)d_in[0];
    const int*   lvl  = (const int*)d_in[1];
    const int*   ei   = (const int*)d_in[2];
    const float* Ws   = (const float*)d_in[3];
    const float* Wt   = (const float*)d_in[4];
    const float* hsW  = (const float*)d_in[5];
    const float* hsb  = (const float*)d_in[6];
    const float* w1   = (const float*)d_in[7];
    const float* b1   = (const float*)d_in[8];
    const float* w2   = (const float*)d_in[9];
    const float* b2   = (const float*)d_in[10];
    const float* w3   = (const float*)d_in[11];
    const float* b3   = (const float*)d_in[12];
    const float* wih  = (const float*)d_in[13];
    // d_in[14] = gru_whh: provably unused (h_old == 0 for every updated node)
    const float* bih  = (const float*)d_in[15];
    const float* bhh  = (const float*)d_in[16];
    float* out = (float*)d_out;   // [0, NH) = hs, [NH, 2NH) = hf

    setupA_k<<<1176, 128>>>(Ws, Wt, hsW, hsb, b3, wih, w3);
    setupB_k<<<1442, 128>>>(gate, lvl, ei, w1, b1, wih, out);
    zmsg_k<<<2048, 128>>>();

    for (int level = 1; level < 8; level++) {
        emlp_k<<<dim3(288, 3), 64>>>(level, ei, gate, w1, w2, b2, out);
        gru_k<<<dim3(144, 3), 128>>>(level, bih, bhh, out + NH);
    }
}